// round 15
// baseline (speedup 1.0000x reference)
#include <cuda_runtime.h>
#include <cuda_fp16.h>
#include <cstdint>
#include <math.h>

// ----------------------------------------------------------------------------
// Problem constants
// ----------------------------------------------------------------------------
#define BATCH 8192
#define FDIM  256
#define NBL   8
#define BF    (BATCH * FDIM)   // 2,097,152

// GEMM tiling (mma.sync m16n8k16 fp16), KT=64 K-chunks, dynamic smem
#define TM 128
#define TN 64
#define KT 64
#define SPADH 72               // padded smem row stride (halves); 36w%32 -> 4gq+tq perm

#define STG_H  (TM * SPADH + 2 * TN * SPADH)   // 18432 halves per stage
#define STG_B  (STG_H * 2)                     // 36864 bytes
#define GEMM_SMEM (2 * STG_B)                  // 73728 bytes

// ----------------------------------------------------------------------------
// Scratch (device globals; no allocation allowed)
// ----------------------------------------------------------------------------
__device__ __half g_xt[(size_t)NBL * BF];   // planes [i][b][k], fp16
__device__ __half g_lp[(size_t)NBL * BF];   // left planes  [i][b][n], fp16
__device__ __half g_rp[(size_t)NBL * BF];   // right planes [i][b][n], fp16
__device__ __half g_wl[4 * FDIM * FDIM];    // [g][n][k] fp16
__device__ __half g_wr[4 * FDIM * FDIM];    // [g][n][k] fp16

// ----------------------------------------------------------------------------
// helpers (base-ISA only: mma.sync + cp.async; no tcgen05 on this target)
// ----------------------------------------------------------------------------
__device__ __forceinline__ uint32_t smem_u32(const void* p) {
    uint32_t a;
    asm("{ .reg .u64 t; cvta.to.shared.u64 t, %1; cvt.u32.u64 %0, t; }"
        : "=r"(a) : "l"(p));
    return a;
}

__device__ __forceinline__ void cp16(uint32_t s, const void* g) {
    asm volatile("cp.async.cg.shared.global [%0], [%1], 16;" :: "r"(s), "l"(g));
}

#define CP_COMMIT() asm volatile("cp.async.commit_group;" ::: "memory")
#define CP_WAIT(n)  asm volatile("cp.async.wait_group %0;" :: "n"(n) : "memory")

#define MMA_FP16(d, a, b0r, b1r) \
    asm volatile( \
        "mma.sync.aligned.m16n8k16.row.col.f32.f16.f16.f32 " \
        "{%0,%1,%2,%3}, {%4,%5,%6,%7}, {%8,%9}, {%0,%1,%2,%3};" \
        : "+f"((d)[0]), "+f"((d)[1]), "+f"((d)[2]), "+f"((d)[3]) \
        : "r"((a)[0]), "r"((a)[1]), "r"((a)[2]), "r"((a)[3]), \
          "r"(b0r), "r"(b1r))

// ----------------------------------------------------------------------------
// Kernel 1: transpose x [B,F,8] -> fp16 planes [i][b][k]; 2 points/thread,
// half2 stores (full 4B coalescing).
// ----------------------------------------------------------------------------
__global__ void __launch_bounds__(256) k_transpose_x(
    const float* __restrict__ x, __half* __restrict__ xt)
{
    int t = (blockIdx.x * 256 + threadIdx.x) * 2;   // t = b*FDIM + k, even
    size_t src = (size_t)t * NBL;
    float4 a0 = *(const float4*)&x[src];
    float4 a1 = *(const float4*)&x[src + 4];
    float4 b0 = *(const float4*)&x[src + 8];
    float4 b1 = *(const float4*)&x[src + 12];
    *(__half2*)&xt[0 * (size_t)BF + t] = __floats2half2_rn(a0.x, b0.x);
    *(__half2*)&xt[1 * (size_t)BF + t] = __floats2half2_rn(a0.y, b0.y);
    *(__half2*)&xt[2 * (size_t)BF + t] = __floats2half2_rn(a0.z, b0.z);
    *(__half2*)&xt[3 * (size_t)BF + t] = __floats2half2_rn(a0.w, b0.w);
    *(__half2*)&xt[4 * (size_t)BF + t] = __floats2half2_rn(a1.x, b1.x);
    *(__half2*)&xt[5 * (size_t)BF + t] = __floats2half2_rn(a1.y, b1.y);
    *(__half2*)&xt[6 * (size_t)BF + t] = __floats2half2_rn(a1.z, b1.z);
    *(__half2*)&xt[7 * (size_t)BF + t] = __floats2half2_rn(a1.w, b1.w);
}

// ----------------------------------------------------------------------------
// Kernel 2: de-interleave weights [n, k, 4] -> fp16 [g][n][k]
// ----------------------------------------------------------------------------
__global__ void __launch_bounds__(256) k_prep_w(
    const float* __restrict__ wl, const float* __restrict__ wr,
    __half* __restrict__ wlt, __half* __restrict__ wrt)
{
    int t = blockIdx.x * 256 + threadIdx.x;   // t = n*FDIM + k
    size_t src = (size_t)t * 4;
    float4 a = *(const float4*)&wl[src];
    float4 b = *(const float4*)&wr[src];
    wlt[0 * FDIM * FDIM + t] = __float2half_rn(a.x);
    wlt[1 * FDIM * FDIM + t] = __float2half_rn(a.y);
    wlt[2 * FDIM * FDIM + t] = __float2half_rn(a.z);
    wlt[3 * FDIM * FDIM + t] = __float2half_rn(a.w);
    wrt[0 * FDIM * FDIM + t] = __float2half_rn(b.x);
    wrt[1 * FDIM * FDIM + t] = __float2half_rn(b.y);
    wrt[2 * FDIM * FDIM + t] = __float2half_rn(b.z);
    wrt[3 * FDIM * FDIM + t] = __float2half_rn(b.w);
}

// ----------------------------------------------------------------------------
// Kernel 3: fp16 mma.sync dual GEMM, KT=64 chunks, 2-stage cp.async pipeline.
// Same verified fragment mapping as the 145.8us kernel (SPADH 40 -> 72).
// ----------------------------------------------------------------------------
__global__ void __launch_bounds__(256, 2) k_gemm_mma(
    const __half* __restrict__ xt,
    const __half* __restrict__ wlt, const __half* __restrict__ wrt,
    __half* __restrict__ lp, __half* __restrict__ rp)
{
    extern __shared__ __half tiles[];

    const int tid  = threadIdx.x;
    const int lane = tid & 31;
    const int w    = tid >> 5;
    const int gq   = lane >> 2;
    const int tq   = lane & 3;

    const int blade = blockIdx.z;
    const int grd = (blade == 0) ? 0 : (blade < 4) ? 1 : (blade < 7) ? 2 : 3;
    const int b0  = blockIdx.x * TM;
    const int n0c = blockIdx.y * TN;

    const __half* Ap  = xt  + (size_t)blade * BF + (size_t)b0 * FDIM;
    const __half* WLp = wlt + (size_t)grd * FDIM * FDIM + (size_t)n0c * FDIM;
    const __half* WRp = wrt + (size_t)grd * FDIM * FDIM + (size_t)n0c * FDIM;

    const uint32_t sT = smem_u32(tiles);

    const int mw = w >> 1;
    const int nw = w & 1;
    const int m0 = mw * 32;
    const int n0w = nw * 32;

    // cp.async thread assignments: rows of 64 halves = 8 x 16B chunks
    const int crow = tid >> 3;        // 0..31
    const int cq   = tid & 7;         // chunk in row

    float acc[2][2][4][4];
#pragma unroll
    for (int o = 0; o < 2; o++)
#pragma unroll
        for (int mi = 0; mi < 2; mi++)
#pragma unroll
            for (int ni = 0; ni < 4; ni++)
#pragma unroll
                for (int q = 0; q < 4; q++) acc[o][mi][ni][q] = 0.f;

#define ISSUE(cc) do { \
    const int s_ = (cc) & 1; \
    const int kt_ = (cc) * KT; \
    const uint32_t ab_ = sT + s_ * STG_B; \
    _Pragma("unroll") \
    for (int it = 0; it < 4; it++) \
        cp16(ab_ + ((it * 32 + crow) * SPADH + cq * 8) * 2, \
             Ap + (size_t)(it * 32 + crow) * FDIM + kt_ + cq * 8); \
    _Pragma("unroll") \
    for (int it2 = 0; it2 < 2; it2++) { \
        cp16(ab_ + (TM * SPADH + (it2 * 32 + crow) * SPADH + cq * 8) * 2, \
             WLp + (size_t)(it2 * 32 + crow) * FDIM + kt_ + cq * 8); \
        cp16(ab_ + ((TM + TN) * SPADH + (it2 * 32 + crow) * SPADH + cq * 8) * 2, \
             WRp + (size_t)(it2 * 32 + crow) * FDIM + kt_ + cq * 8); \
    } \
} while (0)

    ISSUE(0);
    CP_COMMIT();

    for (int c = 0; c < FDIM / KT; c++) {
        if (c < FDIM / KT - 1) {
            ISSUE(c + 1);
            CP_COMMIT();
            CP_WAIT(1);
        } else {
            CP_WAIT(0);
        }
        __syncthreads();

        const __half* As  = tiles + (c & 1) * STG_H;
        const __half* BLs = As + TM * SPADH;
        const __half* BRs = BLs + TN * SPADH;

#pragma unroll
        for (int ks = 0; ks < KT / 16; ks++) {
            const int kk = ks * 16 + 2 * tq;
            uint32_t a[2][4];
#pragma unroll
            for (int mi = 0; mi < 2; mi++) {
                const __half* ab = &As[(m0 + mi * 16 + gq) * SPADH + kk];
                a[mi][0] = *(const uint32_t*)(ab);
                a[mi][1] = *(const uint32_t*)(ab + 8 * SPADH);
                a[mi][2] = *(const uint32_t*)(ab + 8);
                a[mi][3] = *(const uint32_t*)(ab + 8 * SPADH + 8);
            }
#pragma unroll
            for (int ni = 0; ni < 4; ni++) {
                const __half* blp = &BLs[(n0w + ni * 8 + gq) * SPADH + kk];
                uint32_t bl0 = *(const uint32_t*)(blp);
                uint32_t bl1 = *(const uint32_t*)(blp + 8);
                const __half* brp = &BRs[(n0w + ni * 8 + gq) * SPADH + kk];
                uint32_t br0 = *(const uint32_t*)(brp);
                uint32_t br1 = *(const uint32_t*)(brp + 8);
#pragma unroll
                for (int mi = 0; mi < 2; mi++) {
                    MMA_FP16(acc[0][mi][ni], a[mi], bl0, bl1);
                    MMA_FP16(acc[1][mi][ni], a[mi], br0, br1);
                }
            }
        }
        __syncthreads();
    }
#undef ISSUE

    // epilogue: fp16 half2 writes
#pragma unroll
    for (int o = 0; o < 2; o++) {
        __half* base = (o ? rp : lp) + (size_t)blade * BF;
#pragma unroll
        for (int mi = 0; mi < 2; mi++) {
            int row = b0 + m0 + mi * 16 + gq;
#pragma unroll
            for (int ni = 0; ni < 4; ni++) {
                int col = n0c + n0w + ni * 8 + tq * 2;
                *(__half2*)&base[(size_t)row * FDIM + col] =
                    __floats2half2_rn(acc[o][mi][ni][0], acc[o][mi][ni][1]);
                *(__half2*)&base[(size_t)(row + 8) * FDIM + col] =
                    __floats2half2_rn(acc[o][mi][ni][2], acc[o][mi][ni][3]);
            }
        }
    }
}

// ----------------------------------------------------------------------------
// Kernel 4: pointwise — params staged in smem (kills scattered-LDG sector
// explosion: n = tid for every block, so staging reads are fully coalesced).
// ----------------------------------------------------------------------------
__global__ void __launch_bounds__(256) k_pointwise(
    const float* __restrict__ x,
    const __half* __restrict__ lp, const __half* __restrict__ rp,
    const float* __restrict__ b_left, const float* __restrict__ a_norm,
    const float* __restrict__ w_gp, float* __restrict__ out)
{
    __shared__ float s_wg[256 * 21];   // padded 20->21: stride 21 mod 32 coprime
    __shared__ float s_an[256 * 5];    // padded 4->5
    __shared__ float s_bl[256];

    const int tid = threadIdx.x;
    // coalesced staging (identical for every block; L2-resident)
    for (int i = tid; i < 256 * 20; i += 256)
        s_wg[(i / 20) * 21 + (i % 20)] = w_gp[i];
    for (int i = tid; i < 256 * 4; i += 256)
        s_an[(i >> 2) * 5 + (i & 3)] = a_norm[i];
    s_bl[tid] = b_left[tid];
    __syncthreads();

    const int MASKv[8] = {0, 1, 2, 4, 3, 5, 6, 7};
    const int IDXv[8]  = {0, 1, 2, 4, 3, 5, 6, 7};
    const int GRDv[8]  = {0, 1, 1, 1, 2, 2, 2, 3};
    const signed char PIDXv[4][4][4] = {
        { { 0,-1,-1,-1}, {-1, 1,-1,-1}, {-1,-1, 2,-1}, {-1,-1,-1, 3} },
        { {-1, 4,-1,-1}, { 5,-1, 6,-1}, {-1, 7,-1, 8}, {-1,-1, 9,-1} },
        { {-1,-1,10,-1}, {-1,11,-1,12}, {13,-1,14,-1}, {-1,15,-1,-1} },
        { {-1,-1,-1,16}, {-1,-1,17,-1}, {-1,18,-1,-1}, {19,-1,-1,-1} },
    };

    int t = blockIdx.x * 256 + tid;   // t = b*FDIM + n, n == tid
    const int n = tid;

    float xr[8], lf[8], xv[8];
#pragma unroll
    for (int i = 0; i < 8; i++) {
        xr[i] = __half2float(rp[(size_t)i * BF + t]);
        lf[i] = __half2float(lp[(size_t)i * BF + t]);
    }
    {
        float4 v0 = *(const float4*)&x[(size_t)t * 8];
        float4 v1 = *(const float4*)&x[(size_t)t * 8 + 4];
        xv[0] = v0.x; xv[1] = v0.y; xv[2] = v0.z; xv[3] = v0.w;
        xv[4] = v1.x; xv[5] = v1.y; xv[6] = v1.z; xv[7] = v1.w;
    }

    float qs[4];
    qs[0] = xr[0] * xr[0];
    qs[1] = xr[1] * xr[1] + xr[2] * xr[2] + xr[3] * xr[3];
    qs[2] = xr[4] * xr[4] + xr[5] * xr[5] + xr[6] * xr[6];
    qs[3] = xr[7] * xr[7];

    float invn[4];
#pragma unroll
    for (int gg = 0; gg < 4; gg++) {
        float nrm = sqrtf(sqrtf(qs[gg] * qs[gg] + 1e-16f));
        float sig = 1.0f / (1.0f + expf(-s_an[n * 5 + gg]));
        invn[gg] = 1.0f / (sig * (nrm - 1.0f) + 1.0f + 1e-6f);
    }

    float xrn[8];
    xrn[0] = xr[0] * invn[0];
    xrn[1] = xr[1] * invn[1];
    xrn[2] = xr[2] * invn[1];
    xrn[3] = xr[3] * invn[1];
    xrn[4] = xr[4] * invn[2];
    xrn[5] = xr[5] * invn[2];
    xrn[6] = xr[6] * invn[2];
    xrn[7] = xr[7] * invn[3];

    float wp[20];
#pragma unroll
    for (int p = 0; p < 20; p++) wp[p] = s_wg[n * 21 + p];

    float gp[8];
#pragma unroll
    for (int j = 0; j < 8; j++) gp[j] = 0.f;

#pragma unroll
    for (int i = 0; i < 8; i++) {
#pragma unroll
        for (int k = 0; k < 8; k++) {
            const int mi = MASKv[i];
            const int mk = MASKv[k];
            const int j = IDXv[mi ^ mk];
            const int s1 = ((mi >> 1) & mk);
            const int s2 = ((mi >> 2) & mk);
            const int sgn = ((s1 & 1) + ((s1 >> 1) & 1) + ((s1 >> 2) & 1)
                           + (s2 & 1) + ((s2 >> 1) & 1) + ((s2 >> 2) & 1)) & 1;
            const int p = PIDXv[GRDv[i]][GRDv[j]][GRDv[k]];
            float term = xv[i] * xrn[k];
            float ww = wp[p];
            gp[j] += sgn ? (-ww * term) : (ww * term);
        }
    }

    lf[0] += s_bl[n];

    const float rs2 = 0.70710678118654752440f;
    float4 o0 = make_float4((lf[0] + gp[0]) * rs2, (lf[1] + gp[1]) * rs2,
                            (lf[2] + gp[2]) * rs2, (lf[3] + gp[3]) * rs2);
    float4 o1 = make_float4((lf[4] + gp[4]) * rs2, (lf[5] + gp[5]) * rs2,
                            (lf[6] + gp[6]) * rs2, (lf[7] + gp[7]) * rs2);
    *(float4*)&out[(size_t)t * 8] = o0;
    *(float4*)&out[(size_t)t * 8 + 4] = o1;
}

// ----------------------------------------------------------------------------
// Launch — inputs (metadata order): x, w_left, b_left, w_right, a_norm, w_gp
// ----------------------------------------------------------------------------
extern "C" void kernel_launch(void* const* d_in, const int* in_sizes, int n_in,
                              void* d_out, int out_size)
{
    const float* x       = (const float*)d_in[0];
    const float* w_left  = (const float*)d_in[1];
    const float* b_left  = (const float*)d_in[2];
    const float* w_right = (const float*)d_in[3];
    const float* a_norm  = (const float*)d_in[4];
    const float* w_gp    = (const float*)d_in[5];
    float* out = (float*)d_out;

    __half *xt, *wlt, *wrt, *lp, *rp;
    cudaGetSymbolAddress((void**)&xt,  g_xt);
    cudaGetSymbolAddress((void**)&lp,  g_lp);
    cudaGetSymbolAddress((void**)&rp,  g_rp);
    cudaGetSymbolAddress((void**)&wlt, g_wl);
    cudaGetSymbolAddress((void**)&wrt, g_wr);

    cudaFuncSetAttribute(k_gemm_mma, cudaFuncAttributeMaxDynamicSharedMemorySize,
                         GEMM_SMEM);

    k_transpose_x<<<BF / 512, 256>>>(x, xt);
    k_prep_w<<<(FDIM * FDIM) / 256, 256>>>(w_left, w_right, wlt, wrt);

    dim3 gg(BATCH / TM, FDIM / TN, NBL);
    k_gemm_mma<<<gg, 256, GEMM_SMEM>>>(xt, wlt, wrt, lp, rp);

    k_pointwise<<<BF / 256, 256>>>(x, lp, rp, b_left, a_norm, w_gp, out);
}

// round 16
// speedup vs baseline: 1.4635x; 1.4635x over previous
#include <cuda_runtime.h>
#include <cuda_fp16.h>
#include <cstdint>
#include <math.h>

// ----------------------------------------------------------------------------
// Problem constants
// ----------------------------------------------------------------------------
#define BATCH 8192
#define FDIM  256
#define NBL   8
#define BF    (BATCH * FDIM)   // 2,097,152

// GEMM tiling (mma.sync m16n8k16 fp16), KT=64 chunks, 3-stage cp.async
#define TM 128
#define TN 64
#define KT 64
#define NCH (FDIM / KT)        // 4
#define SPADH 72               // padded smem row stride (halves)

#define STG_H  ((TM + 2 * TN) * SPADH)   // 18432 halves per stage
#define STG_B  (STG_H * 2)               // 36864 bytes
#define GEMM_SMEM (3 * STG_B)            // 110592 bytes (x2 CTA = 221KB, fits)

// ----------------------------------------------------------------------------
// Scratch (device globals; no allocation allowed)
// ----------------------------------------------------------------------------
__device__ __half g_xt[(size_t)NBL * BF];   // planes [i][b][k], fp16
__device__ __half g_lp[(size_t)NBL * BF];   // left planes  [i][b][n], fp16
__device__ __half g_rp[(size_t)NBL * BF];   // right planes [i][b][n], fp16
__device__ __half g_wl[4 * FDIM * FDIM];    // [g][n][k] fp16
__device__ __half g_wr[4 * FDIM * FDIM];    // [g][n][k] fp16

// ----------------------------------------------------------------------------
// helpers (base-ISA only: mma.sync + cp.async + ldmatrix)
// ----------------------------------------------------------------------------
__device__ __forceinline__ uint32_t smem_u32(const void* p) {
    uint32_t a;
    asm("{ .reg .u64 t; cvta.to.shared.u64 t, %1; cvt.u32.u64 %0, t; }"
        : "=r"(a) : "l"(p));
    return a;
}

__device__ __forceinline__ void cp16(uint32_t s, const void* g) {
    asm volatile("cp.async.cg.shared.global [%0], [%1], 16;" :: "r"(s), "l"(g));
}

#define CP_COMMIT() asm volatile("cp.async.commit_group;" ::: "memory")
#define CP_WAIT(n)  asm volatile("cp.async.wait_group %0;" :: "n"(n) : "memory")

#define LDSM4(r, addr) \
    asm volatile("ldmatrix.sync.aligned.m8n8.x4.shared.b16 {%0,%1,%2,%3}, [%4];" \
        : "=r"((r)[0]), "=r"((r)[1]), "=r"((r)[2]), "=r"((r)[3]) : "r"(addr))

#define MMA_FP16(d, a, b0r, b1r) \
    asm volatile( \
        "mma.sync.aligned.m16n8k16.row.col.f32.f16.f16.f32 " \
        "{%0,%1,%2,%3}, {%4,%5,%6,%7}, {%8,%9}, {%0,%1,%2,%3};" \
        : "+f"((d)[0]), "+f"((d)[1]), "+f"((d)[2]), "+f"((d)[3]) \
        : "r"((a)[0]), "r"((a)[1]), "r"((a)[2]), "r"((a)[3]), \
          "r"(b0r), "r"(b1r))

// ----------------------------------------------------------------------------
// Kernel 1: transpose x [B,F,8] -> fp16 planes; 2 points/thread, half2 stores
// ----------------------------------------------------------------------------
__global__ void __launch_bounds__(256) k_transpose_x(
    const float* __restrict__ x, __half* __restrict__ xt)
{
    int t = (blockIdx.x * 256 + threadIdx.x) * 2;
    size_t src = (size_t)t * NBL;
    float4 a0 = *(const float4*)&x[src];
    float4 a1 = *(const float4*)&x[src + 4];
    float4 b0 = *(const float4*)&x[src + 8];
    float4 b1 = *(const float4*)&x[src + 12];
    *(__half2*)&xt[0 * (size_t)BF + t] = __floats2half2_rn(a0.x, b0.x);
    *(__half2*)&xt[1 * (size_t)BF + t] = __floats2half2_rn(a0.y, b0.y);
    *(__half2*)&xt[2 * (size_t)BF + t] = __floats2half2_rn(a0.z, b0.z);
    *(__half2*)&xt[3 * (size_t)BF + t] = __floats2half2_rn(a0.w, b0.w);
    *(__half2*)&xt[4 * (size_t)BF + t] = __floats2half2_rn(a1.x, b1.x);
    *(__half2*)&xt[5 * (size_t)BF + t] = __floats2half2_rn(a1.y, b1.y);
    *(__half2*)&xt[6 * (size_t)BF + t] = __floats2half2_rn(a1.z, b1.z);
    *(__half2*)&xt[7 * (size_t)BF + t] = __floats2half2_rn(a1.w, b1.w);
}

// ----------------------------------------------------------------------------
// Kernel 2: de-interleave weights [n, k, 4] -> fp16 [g][n][k]
// ----------------------------------------------------------------------------
__global__ void __launch_bounds__(256) k_prep_w(
    const float* __restrict__ wl, const float* __restrict__ wr,
    __half* __restrict__ wlt, __half* __restrict__ wrt)
{
    int t = blockIdx.x * 256 + threadIdx.x;
    size_t src = (size_t)t * 4;
    float4 a = *(const float4*)&wl[src];
    float4 b = *(const float4*)&wr[src];
    wlt[0 * FDIM * FDIM + t] = __float2half_rn(a.x);
    wlt[1 * FDIM * FDIM + t] = __float2half_rn(a.y);
    wlt[2 * FDIM * FDIM + t] = __float2half_rn(a.z);
    wlt[3 * FDIM * FDIM + t] = __float2half_rn(a.w);
    wrt[0 * FDIM * FDIM + t] = __float2half_rn(b.x);
    wrt[1 * FDIM * FDIM + t] = __float2half_rn(b.y);
    wrt[2 * FDIM * FDIM + t] = __float2half_rn(b.z);
    wrt[3 * FDIM * FDIM + t] = __float2half_rn(b.w);
}

// ----------------------------------------------------------------------------
// Kernel 3: fp16 mma.sync dual GEMM; ldmatrix fragments, 3-stage pipeline,
// one __syncthreads per chunk.
// ----------------------------------------------------------------------------
__global__ void __launch_bounds__(256, 2) k_gemm_mma(
    const __half* __restrict__ xt,
    const __half* __restrict__ wlt, const __half* __restrict__ wrt,
    __half* __restrict__ lp, __half* __restrict__ rp)
{
    extern __shared__ __half tiles[];
    const uint32_t sT = smem_u32(tiles);

    const int tid  = threadIdx.x;
    const int lane = tid & 31;
    const int w    = tid >> 5;
    const int gq   = lane >> 2;
    const int tq   = lane & 3;

    const int blade = blockIdx.z;
    const int grd = (blade == 0) ? 0 : (blade < 4) ? 1 : (blade < 7) ? 2 : 3;
    const int b0  = blockIdx.x * TM;
    const int n0c = blockIdx.y * TN;

    const __half* Ap  = xt  + (size_t)blade * BF + (size_t)b0 * FDIM;
    const __half* WLp = wlt + (size_t)grd * FDIM * FDIM + (size_t)n0c * FDIM;
    const __half* WRp = wrt + (size_t)grd * FDIM * FDIM + (size_t)n0c * FDIM;

    const int m0  = (w >> 1) * 32;
    const int n0w = (w & 1) * 32;

    // cp.async assignments: rows of 64 halves = 8 x 16B chunks
    const int crow = tid >> 3;
    const int cq   = tid & 7;

    // ldmatrix lane address components (halves)
    const int a_lr = lane & 15;                         // A: mats (r0-15,k0),(r0-15,k8)
    const int a_lk = ((lane >> 4) & 1) * 8;
    const int b_lr = (lane & 7) + ((lane >> 4) & 1) * 8; // B: (n0-7,k0),(n0-7,k8),(n8-15,k0),(n8-15,k8)
    const int b_lk = ((lane >> 3) & 1) * 8;

    float acc[2][2][4][4];
#pragma unroll
    for (int o = 0; o < 2; o++)
#pragma unroll
        for (int mi = 0; mi < 2; mi++)
#pragma unroll
            for (int ni = 0; ni < 4; ni++)
#pragma unroll
                for (int q = 0; q < 4; q++) acc[o][mi][ni][q] = 0.f;

#define ISSUE(cc) do { \
    const int s_ = (cc) % 3; \
    const int kt_ = (cc) * KT; \
    const uint32_t ab_ = sT + s_ * STG_B; \
    _Pragma("unroll") \
    for (int it = 0; it < 4; it++) \
        cp16(ab_ + ((it * 32 + crow) * SPADH + cq * 8) * 2, \
             Ap + (size_t)(it * 32 + crow) * FDIM + kt_ + cq * 8); \
    _Pragma("unroll") \
    for (int it2 = 0; it2 < 2; it2++) { \
        cp16(ab_ + (TM * SPADH + (it2 * 32 + crow) * SPADH + cq * 8) * 2, \
             WLp + (size_t)(it2 * 32 + crow) * FDIM + kt_ + cq * 8); \
        cp16(ab_ + ((TM + TN) * SPADH + (it2 * 32 + crow) * SPADH + cq * 8) * 2, \
             WRp + (size_t)(it2 * 32 + crow) * FDIM + kt_ + cq * 8); \
    } \
} while (0)

    ISSUE(0); CP_COMMIT();
    ISSUE(1); CP_COMMIT();

    for (int c = 0; c < NCH; c++) {
        if (c == NCH - 1) { CP_WAIT(0); } else { CP_WAIT(1); }
        __syncthreads();                    // all warps done with stage (c)%3's predecessor
        if (c + 2 < NCH) { ISSUE(c + 2); CP_COMMIT(); }

        const uint32_t st = sT + (c % 3) * STG_B;

#pragma unroll
        for (int ks = 0; ks < KT / 16; ks++) {
            const int kb = ks * 16;
            uint32_t af[2][4];
            LDSM4(af[0], st + ((m0 + a_lr) * SPADH + kb + a_lk) * 2);
            LDSM4(af[1], st + ((m0 + 16 + a_lr) * SPADH + kb + a_lk) * 2);
            uint32_t bfL[2][4], bfR[2][4];
            LDSM4(bfL[0], st + ((TM + n0w + b_lr) * SPADH + kb + b_lk) * 2);
            LDSM4(bfL[1], st + ((TM + n0w + 16 + b_lr) * SPADH + kb + b_lk) * 2);
            LDSM4(bfR[0], st + ((TM + TN + n0w + b_lr) * SPADH + kb + b_lk) * 2);
            LDSM4(bfR[1], st + ((TM + TN + n0w + 16 + b_lr) * SPADH + kb + b_lk) * 2);
#pragma unroll
            for (int ni = 0; ni < 4; ni++) {
                uint32_t bl0 = bfL[ni >> 1][(ni & 1) * 2];
                uint32_t bl1 = bfL[ni >> 1][(ni & 1) * 2 + 1];
                uint32_t br0 = bfR[ni >> 1][(ni & 1) * 2];
                uint32_t br1 = bfR[ni >> 1][(ni & 1) * 2 + 1];
#pragma unroll
                for (int mi = 0; mi < 2; mi++) {
                    MMA_FP16(acc[0][mi][ni], af[mi], bl0, bl1);
                    MMA_FP16(acc[1][mi][ni], af[mi], br0, br1);
                }
            }
        }
    }
#undef ISSUE

    // epilogue: fp16 half2 writes (same verified mapping)
#pragma unroll
    for (int o = 0; o < 2; o++) {
        __half* base = (o ? rp : lp) + (size_t)blade * BF;
#pragma unroll
        for (int mi = 0; mi < 2; mi++) {
            int row = b0 + m0 + mi * 16 + gq;
#pragma unroll
            for (int ni = 0; ni < 4; ni++) {
                int col = n0c + n0w + ni * 8 + tq * 2;
                *(__half2*)&base[(size_t)row * FDIM + col] =
                    __floats2half2_rn(acc[o][mi][ni][0], acc[o][mi][ni][1]);
                *(__half2*)&base[(size_t)(row + 8) * FDIM + col] =
                    __floats2half2_rn(acc[o][mi][ni][2], acc[o][mi][ni][3]);
            }
        }
    }
}

// ----------------------------------------------------------------------------
// Kernel 4: pointwise v3 — 2 batch points per thread (same n), float4 param
// loads, sigmoid hoisted. No smem staging.
// ----------------------------------------------------------------------------
__global__ void __launch_bounds__(256) k_pointwise(
    const float* __restrict__ x,
    const __half* __restrict__ lp, const __half* __restrict__ rp,
    const float* __restrict__ b_left, const float* __restrict__ a_norm,
    const float* __restrict__ w_gp, float* __restrict__ out)
{
    const int MASKv[8] = {0, 1, 2, 4, 3, 5, 6, 7};
    const int IDXv[8]  = {0, 1, 2, 4, 3, 5, 6, 7};
    const int GRDv[8]  = {0, 1, 1, 1, 2, 2, 2, 3};
    const signed char PIDXv[4][4][4] = {
        { { 0,-1,-1,-1}, {-1, 1,-1,-1}, {-1,-1, 2,-1}, {-1,-1,-1, 3} },
        { {-1, 4,-1,-1}, { 5,-1, 6,-1}, {-1, 7,-1, 8}, {-1,-1, 9,-1} },
        { {-1,-1,10,-1}, {-1,11,-1,12}, {13,-1,14,-1}, {-1,15,-1,-1} },
        { {-1,-1,-1,16}, {-1,-1,17,-1}, {-1,18,-1,-1}, {19,-1,-1,-1} },
    };

    const int tid = threadIdx.x;
    const int n = tid;                       // 512-aligned blocks: n == tid
    const int t0 = blockIdx.x * 512 + tid;

    // per-n params, loaded ONCE for both points, vectorized
    float4 anv = __ldg((const float4*)&a_norm[n * 4]);
    float sig[4];
    sig[0] = 1.0f / (1.0f + expf(-anv.x));
    sig[1] = 1.0f / (1.0f + expf(-anv.y));
    sig[2] = 1.0f / (1.0f + expf(-anv.z));
    sig[3] = 1.0f / (1.0f + expf(-anv.w));
    float wp[20];
#pragma unroll
    for (int q = 0; q < 5; q++) {
        float4 v = __ldg((const float4*)&w_gp[n * 20 + q * 4]);
        wp[q * 4 + 0] = v.x; wp[q * 4 + 1] = v.y;
        wp[q * 4 + 2] = v.z; wp[q * 4 + 3] = v.w;
    }
    const float bias = __ldg(&b_left[n]);
    const float rs2 = 0.70710678118654752440f;

#pragma unroll
    for (int pp = 0; pp < 2; pp++) {
        const int t = t0 + pp * 256;

        float xr[8], lf[8], xv[8];
#pragma unroll
        for (int i = 0; i < 8; i++) {
            xr[i] = __half2float(rp[(size_t)i * BF + t]);
            lf[i] = __half2float(lp[(size_t)i * BF + t]);
        }
        {
            float4 v0 = *(const float4*)&x[(size_t)t * 8];
            float4 v1 = *(const float4*)&x[(size_t)t * 8 + 4];
            xv[0] = v0.x; xv[1] = v0.y; xv[2] = v0.z; xv[3] = v0.w;
            xv[4] = v1.x; xv[5] = v1.y; xv[6] = v1.z; xv[7] = v1.w;
        }

        float qs[4];
        qs[0] = xr[0] * xr[0];
        qs[1] = xr[1] * xr[1] + xr[2] * xr[2] + xr[3] * xr[3];
        qs[2] = xr[4] * xr[4] + xr[5] * xr[5] + xr[6] * xr[6];
        qs[3] = xr[7] * xr[7];

        float invn[4];
#pragma unroll
        for (int gg = 0; gg < 4; gg++) {
            float nrm = sqrtf(sqrtf(qs[gg] * qs[gg] + 1e-16f));
            invn[gg] = 1.0f / (sig[gg] * (nrm - 1.0f) + 1.0f + 1e-6f);
        }

        float xrn[8];
        xrn[0] = xr[0] * invn[0];
        xrn[1] = xr[1] * invn[1];
        xrn[2] = xr[2] * invn[1];
        xrn[3] = xr[3] * invn[1];
        xrn[4] = xr[4] * invn[2];
        xrn[5] = xr[5] * invn[2];
        xrn[6] = xr[6] * invn[2];
        xrn[7] = xr[7] * invn[3];

        float gp[8];
#pragma unroll
        for (int j = 0; j < 8; j++) gp[j] = 0.f;
#pragma unroll
        for (int i = 0; i < 8; i++) {
#pragma unroll
            for (int k = 0; k < 8; k++) {
                const int mi = MASKv[i];
                const int mk = MASKv[k];
                const int j = IDXv[mi ^ mk];
                const int s1 = ((mi >> 1) & mk);
                const int s2 = ((mi >> 2) & mk);
                const int sgn = ((s1 & 1) + ((s1 >> 1) & 1) + ((s1 >> 2) & 1)
                               + (s2 & 1) + ((s2 >> 1) & 1) + ((s2 >> 2) & 1)) & 1;
                const int p = PIDXv[GRDv[i]][GRDv[j]][GRDv[k]];
                float term = xv[i] * xrn[k];
                float ww = wp[p];
                gp[j] += sgn ? (-ww * term) : (ww * term);
            }
        }

        lf[0] += bias;

        float4 o0 = make_float4((lf[0] + gp[0]) * rs2, (lf[1] + gp[1]) * rs2,
                                (lf[2] + gp[2]) * rs2, (lf[3] + gp[3]) * rs2);
        float4 o1 = make_float4((lf[4] + gp[4]) * rs2, (lf[5] + gp[5]) * rs2,
                                (lf[6] + gp[6]) * rs2, (lf[7] + gp[7]) * rs2);
        *(float4*)&out[(size_t)t * 8] = o0;
        *(float4*)&out[(size_t)t * 8 + 4] = o1;
    }
}

// ----------------------------------------------------------------------------
// Launch — inputs (metadata order): x, w_left, b_left, w_right, a_norm, w_gp
// ----------------------------------------------------------------------------
extern "C" void kernel_launch(void* const* d_in, const int* in_sizes, int n_in,
                              void* d_out, int out_size)
{
    const float* x       = (const float*)d_in[0];
    const float* w_left  = (const float*)d_in[1];
    const float* b_left  = (const float*)d_in[2];
    const float* w_right = (const float*)d_in[3];
    const float* a_norm  = (const float*)d_in[4];
    const float* w_gp    = (const float*)d_in[5];
    float* out = (float*)d_out;

    __half *xt, *wlt, *wrt, *lp, *rp;
    cudaGetSymbolAddress((void**)&xt,  g_xt);
    cudaGetSymbolAddress((void**)&lp,  g_lp);
    cudaGetSymbolAddress((void**)&rp,  g_rp);
    cudaGetSymbolAddress((void**)&wlt, g_wl);
    cudaGetSymbolAddress((void**)&wrt, g_wr);

    cudaFuncSetAttribute(k_gemm_mma, cudaFuncAttributeMaxDynamicSharedMemorySize,
                         GEMM_SMEM);

    k_transpose_x<<<BF / 512, 256>>>(x, xt);
    k_prep_w<<<(FDIM * FDIM) / 256, 256>>>(w_left, w_right, wlt, wrt);

    dim3 gg(BATCH / TM, FDIM / TN, NBL);
    k_gemm_mma<<<gg, 256, GEMM_SMEM>>>(xt, wlt, wrt, lp, rp);

    k_pointwise<<<BF / 512, 256>>>(x, lp, rp, b_left, a_norm, w_gp, out);
}